// round 6
// baseline (speedup 1.0000x reference)
#include <cuda_runtime.h>
#include <cuda_bf16.h>
#include <math.h>

// Problem constants
#define BATCH 2
#define SEQ   2048
#define DMODEL 1024
#define NHEAD 16
#define HDIM  64
#define MTOK  (BATCH*SEQ)        // 4096 tokens

// ---------------------------------------------------------------------------
// Scratch (device globals; allocation-free)
// ---------------------------------------------------------------------------
__device__ float g_q[MTOK * DMODEL];
__device__ float g_k[MTOK * DMODEL];
__device__ float g_v[MTOK * DMODEL];
__device__ float g_attn[MTOK * DMODEL];

__device__ __forceinline__ unsigned f2tf32(float x) {
    unsigned r;
    asm("cvt.rna.tf32.f32 %0, %1;" : "=r"(r) : "f"(x));
    return r;
}

#define MMA_TF32(acc, a, b0, b1)                                           \
    asm volatile(                                                          \
        "mma.sync.aligned.m16n8k8.row.col.f32.tf32.tf32.f32 "              \
        "{%0,%1,%2,%3}, {%4,%5,%6,%7}, {%8,%9}, {%0,%1,%2,%3};"            \
        : "+f"((acc)[0]), "+f"((acc)[1]), "+f"((acc)[2]), "+f"((acc)[3])   \
        : "r"((a)[0]), "r"((a)[1]), "r"((a)[2]), "r"((a)[3]),              \
          "r"(b0), "r"(b1))

// ---------------------------------------------------------------------------
// TF32 tensor-core GEMM, register-prefetch + smem double buffer.
// C[M,N] = A[M,K] @ W[K,N] + bias. Block tile 128x128x32, 256 thr, 8 warps,
// warp tile 32x64, mma.m16n8k8. Smem holds tf32 (converted once at staging).
// blockIdx.z selects one of up to 3 (A, W, bias, C) problem sets.
// ---------------------------------------------------------------------------
#define GBM 128
#define GBN 128
#define GBK 32
#define ASTR 36     // GBK + 4
#define BSTR 132    // GBN + 4
#define ASZ (GBM * ASTR)      // 4608
#define BSZ (GBK * BSTR)      // 4224
#define GEMM_SMEM ((2 * (ASZ + BSZ)) * (int)sizeof(unsigned))   // 70656 B

__global__ __launch_bounds__(256) void gemm_tf32_rp(
    const float* __restrict__ A0, const float* __restrict__ W0,
    const float* __restrict__ b0p, float* __restrict__ C0,
    const float* __restrict__ A1, const float* __restrict__ W1,
    const float* __restrict__ b1p, float* __restrict__ C1,
    const float* __restrict__ A2, const float* __restrict__ W2,
    const float* __restrict__ b2p, float* __restrict__ C2,
    int M, int N, int K)
{
    extern __shared__ unsigned smu[];
    unsigned* AsB[2] = { smu,           smu + ASZ };
    unsigned* BsB[2] = { smu + 2 * ASZ, smu + 2 * ASZ + BSZ };

    const int z = blockIdx.z;
    const float* A    = (z == 0) ? A0 : (z == 1) ? A1 : A2;
    const float* W    = (z == 0) ? W0 : (z == 1) ? W1 : W2;
    const float* bias = (z == 0) ? b0p : (z == 1) ? b1p : b2p;
    float*       C    = (z == 0) ? C0 : (z == 1) ? C1 : C2;

    const int tid = threadIdx.x;
    const int bm = blockIdx.y * GBM;
    const int bn = blockIdx.x * GBN;

    const int wid  = tid >> 5;
    const int lane = tid & 31;
    const int wm = (wid & 3) * 32;
    const int wn = (wid >> 2) * 64;
    const int gid = lane >> 2;
    const int tg  = lane & 3;

    // staging indices (fixed per thread)
    const int s_ar  = tid >> 1;            // A row 0..127
    const int s_ac  = (tid & 1) * 4;       // A col group {0,4} -> 8 floats/row... 
    // NOTE: A tile is 128x32 floats = 1024 float4; 256 thr * 4 each.
    // Use idx math instead for generality.

    float4 ra[4], rb[4];

    auto ldg_tile = [&](int k0) {
#pragma unroll
        for (int i = 0; i < 4; i++) {
            int idx = i * 256 + tid;
            int r  = idx >> 3;            // 0..127
            int c4 = idx & 7;             // 0..7
            ra[i] = *(const float4*)(A + (size_t)(bm + r) * K + k0 + c4 * 4);
        }
#pragma unroll
        for (int i = 0; i < 4; i++) {
            int idx = i * 256 + tid;
            int k  = idx >> 5;            // 0..31
            int c4 = idx & 31;            // 0..31
            rb[i] = *(const float4*)(W + (size_t)(k0 + k) * N + bn + c4 * 4);
        }
    };

    auto sts_tile = [&](unsigned* As, unsigned* Bs) {
#pragma unroll
        for (int i = 0; i < 4; i++) {
            int idx = i * 256 + tid;
            int r  = idx >> 3;
            int c4 = idx & 7;
            unsigned* d = &As[r * ASTR + c4 * 4];
            d[0] = f2tf32(ra[i].x); d[1] = f2tf32(ra[i].y);
            d[2] = f2tf32(ra[i].z); d[3] = f2tf32(ra[i].w);
        }
#pragma unroll
        for (int i = 0; i < 4; i++) {
            int idx = i * 256 + tid;
            int k  = idx >> 5;
            int c4 = idx & 31;
            unsigned* d = &Bs[k * BSTR + c4 * 4];
            d[0] = f2tf32(rb[i].x); d[1] = f2tf32(rb[i].y);
            d[2] = f2tf32(rb[i].z); d[3] = f2tf32(rb[i].w);
        }
    };

    float acc[2][8][4];
#pragma unroll
    for (int mi = 0; mi < 2; mi++)
#pragma unroll
        for (int ni = 0; ni < 8; ni++)
#pragma unroll
            for (int c = 0; c < 4; c++) acc[mi][ni][c] = 0.f;

    const int nsteps = K / GBK;   // 32

    // prologue: tile0 -> smem buf0; prefetch tile1 into regs
    ldg_tile(0);
    sts_tile(AsB[0], BsB[0]);
    if (nsteps > 1) ldg_tile(GBK);
    __syncthreads();

    for (int s = 0; s < nsteps; s++) {
        const int cur = s & 1;
        const unsigned* As = AsB[cur];
        const unsigned* Bs = BsB[cur];

#pragma unroll
        for (int kk = 0; kk < GBK; kk += 8) {
            unsigned af[2][4];
#pragma unroll
            for (int mi = 0; mi < 2; mi++) {
                int rb2 = wm + mi * 16;
                af[mi][0] = As[(rb2 + gid) * ASTR + kk + tg];
                af[mi][1] = As[(rb2 + gid + 8) * ASTR + kk + tg];
                af[mi][2] = As[(rb2 + gid) * ASTR + kk + tg + 4];
                af[mi][3] = As[(rb2 + gid + 8) * ASTR + kk + tg + 4];
            }
            unsigned bf[8][2];
#pragma unroll
            for (int ni = 0; ni < 8; ni++) {
                int nb = wn + ni * 8 + gid;
                bf[ni][0] = Bs[(kk + tg) * BSTR + nb];
                bf[ni][1] = Bs[(kk + tg + 4) * BSTR + nb];
            }
#pragma unroll
            for (int mi = 0; mi < 2; mi++)
#pragma unroll
                for (int ni = 0; ni < 8; ni++)
                    MMA_TF32(acc[mi][ni], af[mi], bf[ni][0], bf[ni][1]);
        }

        if (s + 1 < nsteps) {
            __syncthreads();   // all warps done reading buf[cur^1] (iter s-1)
            sts_tile(AsB[cur ^ 1], BsB[cur ^ 1]);      // regs hold tile s+1
            if (s + 2 < nsteps) ldg_tile((s + 2) * GBK);  // prefetch tile s+2
            __syncthreads();   // STS visible before next compute
        }
    }

#pragma unroll
    for (int mi = 0; mi < 2; mi++) {
        int row0 = bm + wm + mi * 16 + gid;
#pragma unroll
        for (int ni = 0; ni < 8; ni++) {
            int col = bn + wn + ni * 8 + tg * 2;
            float bb0 = bias[col], bb1 = bias[col + 1];
            float2 v0 = make_float2(acc[mi][ni][0] + bb0, acc[mi][ni][1] + bb1);
            float2 v1 = make_float2(acc[mi][ni][2] + bb0, acc[mi][ni][3] + bb1);
            *(float2*)(C + (size_t)row0 * N + col) = v0;
            *(float2*)(C + (size_t)(row0 + 8) * N + col) = v1;
        }
    }
}

// ---------------------------------------------------------------------------
// Tensor-core flash attention (tf32 mma.m16n8k8).  (unchanged from R4)
// ---------------------------------------------------------------------------
#define ATS 64
#define QSTRD 68
#define KSTRD 68
#define VSTRD 72
#define ATTN_SMEM ((ATS*QSTRD + ATS*KSTRD + ATS*VSTRD + ATS) * (int)sizeof(float))

__global__ __launch_bounds__(128) void attn_mma(
    const float* __restrict__ Q, const float* __restrict__ K,
    const float* __restrict__ V, const unsigned char* __restrict__ maskp,
    float* __restrict__ O)
{
    extern __shared__ float sm[];
    unsigned* Qs = (unsigned*)sm;                    // [64][68]
    unsigned* Ks = Qs + ATS * QSTRD;                 // [64][68]
    unsigned* Vs = Ks + ATS * KSTRD;                 // [64][72]
    float*    Madd = (float*)(Vs + ATS * VSTRD);     // [64]

    const int tid  = threadIdx.x;
    const int qt = blockIdx.x, h = blockIdx.y, b = blockIdx.z;
    const int lane = tid & 31, w = tid >> 5;
    const int gid = lane >> 2, tg = lane & 3;
    const int qb = w * 16;
    const int tok0 = b * SEQ + qt * ATS;

    {
        const float* Qg = Q + (size_t)tok0 * DMODEL + h * HDIM;
#pragma unroll
        for (int i = 0; i < 8; i++) {
            int idx = i * 128 + tid;
            int rr = idx >> 4, c4 = idx & 15;
            float4 v = *(const float4*)(Qg + (size_t)rr * DMODEL + c4 * 4);
            unsigned* dst = &Qs[rr * QSTRD + c4 * 4];
            dst[0] = f2tf32(v.x * 0.125f); dst[1] = f2tf32(v.y * 0.125f);
            dst[2] = f2tf32(v.z * 0.125f); dst[3] = f2tf32(v.w * 0.125f);
        }
    }
    __syncthreads();

    unsigned qa[8][4];
#pragma unroll
    for (int kc = 0; kc < 8; kc++) {
        qa[kc][0] = Qs[(qb + gid)     * QSTRD + kc * 8 + tg];
        qa[kc][1] = Qs[(qb + gid + 8) * QSTRD + kc * 8 + tg];
        qa[kc][2] = Qs[(qb + gid)     * QSTRD + kc * 8 + tg + 4];
        qa[kc][3] = Qs[(qb + gid + 8) * QSTRD + kc * 8 + tg + 4];
    }

    float oa[8][4];
#pragma unroll
    for (int ni = 0; ni < 8; ni++)
#pragma unroll
        for (int c = 0; c < 4; c++) oa[ni][c] = 0.f;

    float mA = -1e30f, mB = -1e30f, lA = 0.f, lB = 0.f;
    const int rowAg = qt * ATS + qb + gid;
    const int rowBg = rowAg + 8;

    for (int kt = 0; kt <= qt; kt++) {
        __syncthreads();
        {
            const float* Kg = K + (size_t)(b * SEQ + kt * ATS) * DMODEL + h * HDIM;
            const float* Vg = V + (size_t)(b * SEQ + kt * ATS) * DMODEL + h * HDIM;
#pragma unroll
            for (int i = 0; i < 8; i++) {
                int idx = i * 128 + tid;
                int rr = idx >> 4, c4 = idx & 15;
                float4 kv = *(const float4*)(Kg + (size_t)rr * DMODEL + c4 * 4);
                unsigned* kd = &Ks[rr * KSTRD + c4 * 4];
                kd[0] = f2tf32(kv.x); kd[1] = f2tf32(kv.y);
                kd[2] = f2tf32(kv.z); kd[3] = f2tf32(kv.w);
                float4 vv = *(const float4*)(Vg + (size_t)rr * DMODEL + c4 * 4);
                unsigned* vd = &Vs[rr * VSTRD + c4 * 4];
                vd[0] = f2tf32(vv.x); vd[1] = f2tf32(vv.y);
                vd[2] = f2tf32(vv.z); vd[3] = f2tf32(vv.w);
            }
            if (tid < ATS)
                Madd[tid] = maskp[b * SEQ + kt * ATS + tid] ? -1e30f : 0.f;
        }
        __syncthreads();

        float sacc[8][4];
#pragma unroll
        for (int ni = 0; ni < 8; ni++)
#pragma unroll
            for (int c = 0; c < 4; c++) sacc[ni][c] = 0.f;
#pragma unroll
        for (int kc = 0; kc < 8; kc++) {
#pragma unroll
            for (int ni = 0; ni < 8; ni++) {
                unsigned b0 = Ks[(ni * 8 + gid) * KSTRD + kc * 8 + tg];
                unsigned b1 = Ks[(ni * 8 + gid) * KSTRD + kc * 8 + tg + 4];
                MMA_TF32(sacc[ni], qa[kc], b0, b1);
            }
        }

        const int kbase = kt * ATS;
        float tmA = -1e30f, tmB = -1e30f;
#pragma unroll
        for (int ni = 0; ni < 8; ni++) {
            int c0 = ni * 8 + 2 * tg, c1 = c0 + 1;
            float m0 = Madd[c0], m1 = Madd[c1];
            sacc[ni][0] += m0; sacc[ni][1] += m1;
            sacc[ni][2] += m0; sacc[ni][3] += m1;
            if (kbase + c0 > rowAg) sacc[ni][0] = -1e30f;
            if (kbase + c1 > rowAg) sacc[ni][1] = -1e30f;
            if (kbase + c0 > rowBg) sacc[ni][2] = -1e30f;
            if (kbase + c1 > rowBg) sacc[ni][3] = -1e30f;
            tmA = fmaxf(tmA, fmaxf(sacc[ni][0], sacc[ni][1]));
            tmB = fmaxf(tmB, fmaxf(sacc[ni][2], sacc[ni][3]));
        }
        tmA = fmaxf(tmA, __shfl_xor_sync(0xffffffffu, tmA, 1));
        tmA = fmaxf(tmA, __shfl_xor_sync(0xffffffffu, tmA, 2));
        tmB = fmaxf(tmB, __shfl_xor_sync(0xffffffffu, tmB, 1));
        tmB = fmaxf(tmB, __shfl_xor_sync(0xffffffffu, tmB, 2));

        float nmA = fmaxf(mA, tmA), nmB = fmaxf(mB, tmB);
        float corrA = (mA > -1e29f) ? __expf(mA - nmA) : 0.f;
        float corrB = (mB > -1e29f) ? __expf(mB - nmB) : 0.f;

        unsigned pu[8][4];
        float saA = 0.f, saB = 0.f;
#pragma unroll
        for (int ni = 0; ni < 8; ni++) {
            float p0 = (sacc[ni][0] > -1e29f) ? __expf(sacc[ni][0] - nmA) : 0.f;
            float p1 = (sacc[ni][1] > -1e29f) ? __expf(sacc[ni][1] - nmA) : 0.f;
            float p2 = (sacc[ni][2] > -1e29f) ? __expf(sacc[ni][2] - nmB) : 0.f;
            float p3 = (sacc[ni][3] > -1e29f) ? __expf(sacc[ni][3] - nmB) : 0.f;
            saA += p0 + p1; saB += p2 + p3;
            pu[ni][0] = f2tf32(p0); pu[ni][1] = f2tf32(p1);
            pu[ni][2] = f2tf32(p2); pu[ni][3] = f2tf32(p3);
        }
        saA += __shfl_xor_sync(0xffffffffu, saA, 1);
        saA += __shfl_xor_sync(0xffffffffu, saA, 2);
        saB += __shfl_xor_sync(0xffffffffu, saB, 1);
        saB += __shfl_xor_sync(0xffffffffu, saB, 2);

        lA = lA * corrA + saA;
        lB = lB * corrB + saB;
        mA = nmA; mB = nmB;
#pragma unroll
        for (int ni = 0; ni < 8; ni++) {
            oa[ni][0] *= corrA; oa[ni][1] *= corrA;
            oa[ni][2] *= corrB; oa[ni][3] *= corrB;
        }

        const int srcbase = lane & ~3;
#pragma unroll
        for (int kc = 0; kc < 8; kc++) {
            int s1 = srcbase + (tg >> 1);
            int s2 = s1 + 2;
            unsigned v00 = __shfl_sync(0xffffffffu, pu[kc][0], s1);
            unsigned v01 = __shfl_sync(0xffffffffu, pu[kc][1], s1);
            unsigned v10 = __shfl_sync(0xffffffffu, pu[kc][2], s1);
            unsigned v11 = __shfl_sync(0xffffffffu, pu[kc][3], s1);
            unsigned w00 = __shfl_sync(0xffffffffu, pu[kc][0], s2);
            unsigned w01 = __shfl_sync(0xffffffffu, pu[kc][1], s2);
            unsigned w10 = __shfl_sync(0xffffffffu, pu[kc][2], s2);
            unsigned w11 = __shfl_sync(0xffffffffu, pu[kc][3], s2);
            unsigned pa[4];
            pa[0] = (tg & 1) ? v01 : v00;
            pa[1] = (tg & 1) ? v11 : v10;
            pa[2] = (tg & 1) ? w01 : w00;
            pa[3] = (tg & 1) ? w11 : w10;
#pragma unroll
            for (int ni = 0; ni < 8; ni++) {
                unsigned b0 = Vs[(kc * 8 + tg)     * VSTRD + ni * 8 + gid];
                unsigned b1 = Vs[(kc * 8 + tg + 4) * VSTRD + ni * 8 + gid];
                MMA_TF32(oa[ni], pa, b0, b1);
            }
        }
    }

    const float rlA = (lA > 0.f) ? (1.f / lA) : 0.f;
    const float rlB = (lB > 0.f) ? (1.f / lB) : 0.f;
    float* Og = O + (size_t)(tok0 + qb + gid) * DMODEL + h * HDIM;
#pragma unroll
    for (int ni = 0; ni < 8; ni++) {
        int col = ni * 8 + 2 * tg;
        float2 vA = make_float2(oa[ni][0] * rlA, oa[ni][1] * rlA);
        float2 vB = make_float2(oa[ni][2] * rlB, oa[ni][3] * rlB);
        *(float2*)(Og + col) = vA;
        *(float2*)(Og + (size_t)8 * DMODEL + col) = vB;
    }
}

// ---------------------------------------------------------------------------
// Launch
// ---------------------------------------------------------------------------
extern "C" void kernel_launch(void* const* d_in, const int* in_sizes, int n_in,
                              void* d_out, int out_size)
{
    const float* queries = (const float*)d_in[0];
    const float* keys    = (const float*)d_in[1];
    const float* values  = (const float*)d_in[2];
    const unsigned char* maskp = (const unsigned char*)d_in[3];
    const float* Wq = (const float*)d_in[4];
    const float* bq = (const float*)d_in[5];
    const float* Wk = (const float*)d_in[6];
    const float* bk = (const float*)d_in[7];
    const float* Wv = (const float*)d_in[8];
    const float* bv = (const float*)d_in[9];
    const float* Wo = (const float*)d_in[10];
    const float* bo = (const float*)d_in[11];
    float* out = (float*)d_out;

    float *qb, *kb, *vb, *ab;
    cudaGetSymbolAddress((void**)&qb, g_q);
    cudaGetSymbolAddress((void**)&kb, g_k);
    cudaGetSymbolAddress((void**)&vb, g_v);
    cudaGetSymbolAddress((void**)&ab, g_attn);

    cudaFuncSetAttribute(gemm_tf32_rp,
                         cudaFuncAttributeMaxDynamicSharedMemorySize, GEMM_SMEM);
    cudaFuncSetAttribute(attn_mma,
                         cudaFuncAttributeMaxDynamicSharedMemorySize, ATTN_SMEM);

    // fused Q/K/V projections (grid.z selects problem)
    dim3 gq(DMODEL / GBN, MTOK / GBM, 3);   // (8, 32, 3)
    gemm_tf32_rp<<<gq, 256, GEMM_SMEM>>>(
        queries, Wq, bq, qb,
        keys,    Wk, bk, kb,
        values,  Wv, bv, vb,
        MTOK, DMODEL, DMODEL);

    dim3 ga(SEQ / ATS, NHEAD, BATCH);       // (32, 16, 2)
    attn_mma<<<ga, 128, ATTN_SMEM>>>(qb, kb, vb, maskp, ab);

    dim3 go(DMODEL / GBN, MTOK / GBM, 1);   // (8, 32, 1)
    gemm_tf32_rp<<<go, 256, GEMM_SMEM>>>(
        ab, Wo, bo, out,
        ab, Wo, bo, out,
        ab, Wo, bo, out,
        MTOK, DMODEL, DMODEL);
}

// round 7
// speedup vs baseline: 1.5356x; 1.5356x over previous
#include <cuda_runtime.h>
#include <cuda_bf16.h>
#include <math.h>

// Problem constants
#define BATCH 2
#define SEQ   2048
#define DMODEL 1024
#define NHEAD 16
#define HDIM  64
#define MTOK  (BATCH*SEQ)        // 4096 tokens

// ---------------------------------------------------------------------------
// Scratch (device globals; allocation-free)
// ---------------------------------------------------------------------------
__device__ float g_q[MTOK * DMODEL];
__device__ float g_k[MTOK * DMODEL];
__device__ float g_v[MTOK * DMODEL];
__device__ float g_attn[MTOK * DMODEL];

__device__ __forceinline__ unsigned f2tf32(float x) {
    unsigned r;
    asm("cvt.rna.tf32.f32 %0, %1;" : "=r"(r) : "f"(x));
    return r;
}

#define MMA_TF32(acc, a, b0, b1)                                           \
    asm volatile(                                                          \
        "mma.sync.aligned.m16n8k8.row.col.f32.tf32.tf32.f32 "              \
        "{%0,%1,%2,%3}, {%4,%5,%6,%7}, {%8,%9}, {%0,%1,%2,%3};"            \
        : "+f"((acc)[0]), "+f"((acc)[1]), "+f"((acc)[2]), "+f"((acc)[3])   \
        : "r"((a)[0]), "r"((a)[1]), "r"((a)[2]), "r"((a)[3]),              \
          "r"(b0), "r"(b1))

// ---------------------------------------------------------------------------
// TF32 tensor-core GEMM (R4 body): C = A@W + bias. 128x128x32 tile, 256 thr,
// 8 warps, warp tile 32x64, mma.m16n8k8. Smem holds tf32 (cvt once at stage).
// __launch_bounds__(256,2) forces <=128 regs -> 2 blocks/SM (16 warps).
// blockIdx.z selects one of up to 3 (A, W, bias, C) problem sets.
// ---------------------------------------------------------------------------
#define GBM 128
#define GBN 128
#define GBK 32
#define ASTR 36
#define BSTR 132

__global__ __launch_bounds__(256, 2) void gemm_tf32(
    const float* __restrict__ A0, const float* __restrict__ W0,
    const float* __restrict__ b0p, float* __restrict__ C0,
    const float* __restrict__ A1, const float* __restrict__ W1,
    const float* __restrict__ b1p, float* __restrict__ C1,
    const float* __restrict__ A2, const float* __restrict__ W2,
    const float* __restrict__ b2p, float* __restrict__ C2,
    int M, int N, int K)
{
    __shared__ unsigned As[GBM * ASTR];   // [m][k]
    __shared__ unsigned Bs[GBK * BSTR];   // [k][n]

    const int z = blockIdx.z;
    const float* A    = (z == 0) ? A0 : (z == 1) ? A1 : A2;
    const float* W    = (z == 0) ? W0 : (z == 1) ? W1 : W2;
    const float* bias = (z == 0) ? b0p : (z == 1) ? b1p : b2p;
    float*       C    = (z == 0) ? C0 : (z == 1) ? C1 : C2;

    const int tid = threadIdx.x;
    const int bm = blockIdx.y * GBM;
    const int bn = blockIdx.x * GBN;

    const int wid  = tid >> 5;
    const int lane = tid & 31;
    const int wm = (wid & 3) * 32;
    const int wn = (wid >> 2) * 64;
    const int gid = lane >> 2;
    const int tg  = lane & 3;

    float acc[2][8][4];
#pragma unroll
    for (int mi = 0; mi < 2; mi++)
#pragma unroll
        for (int ni = 0; ni < 8; ni++)
#pragma unroll
            for (int c = 0; c < 4; c++) acc[mi][ni][c] = 0.f;

    for (int k0 = 0; k0 < K; k0 += GBK) {
#pragma unroll
        for (int i = 0; i < 4; i++) {
            int idx = i * 256 + tid;
            int r  = idx >> 3;
            int c4 = idx & 7;
            float4 v = *(const float4*)(A + (size_t)(bm + r) * K + k0 + c4 * 4);
            unsigned* dst = &As[r * ASTR + c4 * 4];
            dst[0] = f2tf32(v.x); dst[1] = f2tf32(v.y);
            dst[2] = f2tf32(v.z); dst[3] = f2tf32(v.w);
        }
#pragma unroll
        for (int i = 0; i < 4; i++) {
            int idx = i * 256 + tid;
            int k  = idx >> 5;
            int c4 = idx & 31;
            float4 v = *(const float4*)(W + (size_t)(k0 + k) * N + bn + c4 * 4);
            unsigned* dst = &Bs[k * BSTR + c4 * 4];
            dst[0] = f2tf32(v.x); dst[1] = f2tf32(v.y);
            dst[2] = f2tf32(v.z); dst[3] = f2tf32(v.w);
        }
        __syncthreads();

#pragma unroll
        for (int kk = 0; kk < GBK; kk += 8) {
            unsigned af[2][4];
#pragma unroll
            for (int mi = 0; mi < 2; mi++) {
                int rb = wm + mi * 16;
                af[mi][0] = As[(rb + gid) * ASTR + kk + tg];
                af[mi][1] = As[(rb + gid + 8) * ASTR + kk + tg];
                af[mi][2] = As[(rb + gid) * ASTR + kk + tg + 4];
                af[mi][3] = As[(rb + gid + 8) * ASTR + kk + tg + 4];
            }
            unsigned bf[8][2];
#pragma unroll
            for (int ni = 0; ni < 8; ni++) {
                int nb = wn + ni * 8 + gid;
                bf[ni][0] = Bs[(kk + tg) * BSTR + nb];
                bf[ni][1] = Bs[(kk + tg + 4) * BSTR + nb];
            }
#pragma unroll
            for (int mi = 0; mi < 2; mi++)
#pragma unroll
                for (int ni = 0; ni < 8; ni++)
                    MMA_TF32(acc[mi][ni], af[mi], bf[ni][0], bf[ni][1]);
        }
        __syncthreads();
    }

#pragma unroll
    for (int mi = 0; mi < 2; mi++) {
        int row0 = bm + wm + mi * 16 + gid;
#pragma unroll
        for (int ni = 0; ni < 8; ni++) {
            int col = bn + wn + ni * 8 + tg * 2;
            float bb0 = bias[col], bb1 = bias[col + 1];
            float2 v0 = make_float2(acc[mi][ni][0] + bb0, acc[mi][ni][1] + bb1);
            float2 v1 = make_float2(acc[mi][ni][2] + bb0, acc[mi][ni][3] + bb1);
            *(float2*)(C + (size_t)row0 * N + col) = v0;
            *(float2*)(C + (size_t)(row0 + 8) * N + col) = v1;
        }
    }
}

// ---------------------------------------------------------------------------
// Tensor-core flash attention (tf32 mma.m16n8k8), causal-split mainloop.
// Interior key-tiles (kt < qt) skip all causal compares (provably inactive).
// ---------------------------------------------------------------------------
#define ATS 64
#define QSTRD 68
#define KSTRD 68
#define VSTRD 72
#define ATTN_SMEM ((ATS*QSTRD + ATS*KSTRD + ATS*VSTRD + ATS) * (int)sizeof(float))

__global__ __launch_bounds__(128) void attn_mma(
    const float* __restrict__ Q, const float* __restrict__ K,
    const float* __restrict__ V, const unsigned char* __restrict__ maskp,
    float* __restrict__ O)
{
    extern __shared__ float sm[];
    unsigned* Qs = (unsigned*)sm;                    // [64][68]
    unsigned* Ks = Qs + ATS * QSTRD;                 // [64][68]
    unsigned* Vs = Ks + ATS * KSTRD;                 // [64][72]
    float*    Madd = (float*)(Vs + ATS * VSTRD);     // [64]

    const int tid  = threadIdx.x;
    const int qt = blockIdx.x, h = blockIdx.y, b = blockIdx.z;
    const int lane = tid & 31, w = tid >> 5;
    const int gid = lane >> 2, tg = lane & 3;
    const int qb = w * 16;
    const int tok0 = b * SEQ + qt * ATS;

    {
        const float* Qg = Q + (size_t)tok0 * DMODEL + h * HDIM;
#pragma unroll
        for (int i = 0; i < 8; i++) {
            int idx = i * 128 + tid;
            int rr = idx >> 4, c4 = idx & 15;
            float4 v = *(const float4*)(Qg + (size_t)rr * DMODEL + c4 * 4);
            unsigned* dst = &Qs[rr * QSTRD + c4 * 4];
            dst[0] = f2tf32(v.x * 0.125f); dst[1] = f2tf32(v.y * 0.125f);
            dst[2] = f2tf32(v.z * 0.125f); dst[3] = f2tf32(v.w * 0.125f);
        }
    }
    __syncthreads();

    unsigned qa[8][4];
#pragma unroll
    for (int kc = 0; kc < 8; kc++) {
        qa[kc][0] = Qs[(qb + gid)     * QSTRD + kc * 8 + tg];
        qa[kc][1] = Qs[(qb + gid + 8) * QSTRD + kc * 8 + tg];
        qa[kc][2] = Qs[(qb + gid)     * QSTRD + kc * 8 + tg + 4];
        qa[kc][3] = Qs[(qb + gid + 8) * QSTRD + kc * 8 + tg + 4];
    }

    float oa[8][4];
#pragma unroll
    for (int ni = 0; ni < 8; ni++)
#pragma unroll
        for (int c = 0; c < 4; c++) oa[ni][c] = 0.f;

    float mA = -1e30f, mB = -1e30f, lA = 0.f, lB = 0.f;
    const int rowAg = qt * ATS + qb + gid;
    const int rowBg = rowAg + 8;

    auto tile_step = [&](int kt, bool diag) {
        __syncthreads();
        {
            const float* Kg = K + (size_t)(b * SEQ + kt * ATS) * DMODEL + h * HDIM;
            const float* Vg = V + (size_t)(b * SEQ + kt * ATS) * DMODEL + h * HDIM;
#pragma unroll
            for (int i = 0; i < 8; i++) {
                int idx = i * 128 + tid;
                int rr = idx >> 4, c4 = idx & 15;
                float4 kv = *(const float4*)(Kg + (size_t)rr * DMODEL + c4 * 4);
                unsigned* kd = &Ks[rr * KSTRD + c4 * 4];
                kd[0] = f2tf32(kv.x); kd[1] = f2tf32(kv.y);
                kd[2] = f2tf32(kv.z); kd[3] = f2tf32(kv.w);
                float4 vv = *(const float4*)(Vg + (size_t)rr * DMODEL + c4 * 4);
                unsigned* vd = &Vs[rr * VSTRD + c4 * 4];
                vd[0] = f2tf32(vv.x); vd[1] = f2tf32(vv.y);
                vd[2] = f2tf32(vv.z); vd[3] = f2tf32(vv.w);
            }
            if (tid < ATS)
                Madd[tid] = maskp[b * SEQ + kt * ATS + tid] ? -1e30f : 0.f;
        }
        __syncthreads();

        float sacc[8][4];
#pragma unroll
        for (int ni = 0; ni < 8; ni++)
#pragma unroll
            for (int c = 0; c < 4; c++) sacc[ni][c] = 0.f;
#pragma unroll
        for (int kc = 0; kc < 8; kc++) {
#pragma unroll
            for (int ni = 0; ni < 8; ni++) {
                unsigned b0 = Ks[(ni * 8 + gid) * KSTRD + kc * 8 + tg];
                unsigned b1 = Ks[(ni * 8 + gid) * KSTRD + kc * 8 + tg + 4];
                MMA_TF32(sacc[ni], qa[kc], b0, b1);
            }
        }

        const int kbase = kt * ATS;
        float tmA = -1e30f, tmB = -1e30f;
#pragma unroll
        for (int ni = 0; ni < 8; ni++) {
            int c0 = ni * 8 + 2 * tg, c1 = c0 + 1;
            float m0 = Madd[c0], m1 = Madd[c1];
            sacc[ni][0] += m0; sacc[ni][1] += m1;
            sacc[ni][2] += m0; sacc[ni][3] += m1;
            if (diag) {
                if (kbase + c0 > rowAg) sacc[ni][0] = -1e30f;
                if (kbase + c1 > rowAg) sacc[ni][1] = -1e30f;
                if (kbase + c0 > rowBg) sacc[ni][2] = -1e30f;
                if (kbase + c1 > rowBg) sacc[ni][3] = -1e30f;
            }
            tmA = fmaxf(tmA, fmaxf(sacc[ni][0], sacc[ni][1]));
            tmB = fmaxf(tmB, fmaxf(sacc[ni][2], sacc[ni][3]));
        }
        tmA = fmaxf(tmA, __shfl_xor_sync(0xffffffffu, tmA, 1));
        tmA = fmaxf(tmA, __shfl_xor_sync(0xffffffffu, tmA, 2));
        tmB = fmaxf(tmB, __shfl_xor_sync(0xffffffffu, tmB, 1));
        tmB = fmaxf(tmB, __shfl_xor_sync(0xffffffffu, tmB, 2));

        float nmA = fmaxf(mA, tmA), nmB = fmaxf(mB, tmB);
        float corrA = (mA > -1e29f) ? __expf(mA - nmA) : 0.f;
        float corrB = (mB > -1e29f) ? __expf(mB - nmB) : 0.f;

        unsigned pu[8][4];
        float saA = 0.f, saB = 0.f;
#pragma unroll
        for (int ni = 0; ni < 8; ni++) {
            float p0 = (sacc[ni][0] > -1e29f) ? __expf(sacc[ni][0] - nmA) : 0.f;
            float p1 = (sacc[ni][1] > -1e29f) ? __expf(sacc[ni][1] - nmA) : 0.f;
            float p2 = (sacc[ni][2] > -1e29f) ? __expf(sacc[ni][2] - nmB) : 0.f;
            float p3 = (sacc[ni][3] > -1e29f) ? __expf(sacc[ni][3] - nmB) : 0.f;
            saA += p0 + p1; saB += p2 + p3;
            pu[ni][0] = f2tf32(p0); pu[ni][1] = f2tf32(p1);
            pu[ni][2] = f2tf32(p2); pu[ni][3] = f2tf32(p3);
        }
        saA += __shfl_xor_sync(0xffffffffu, saA, 1);
        saA += __shfl_xor_sync(0xffffffffu, saA, 2);
        saB += __shfl_xor_sync(0xffffffffu, saB, 1);
        saB += __shfl_xor_sync(0xffffffffu, saB, 2);

        lA = lA * corrA + saA;
        lB = lB * corrB + saB;
        mA = nmA; mB = nmB;
#pragma unroll
        for (int ni = 0; ni < 8; ni++) {
            oa[ni][0] *= corrA; oa[ni][1] *= corrA;
            oa[ni][2] *= corrB; oa[ni][3] *= corrB;
        }

        const int srcbase = lane & ~3;
#pragma unroll
        for (int kc = 0; kc < 8; kc++) {
            int s1 = srcbase + (tg >> 1);
            int s2 = s1 + 2;
            unsigned v00 = __shfl_sync(0xffffffffu, pu[kc][0], s1);
            unsigned v01 = __shfl_sync(0xffffffffu, pu[kc][1], s1);
            unsigned v10 = __shfl_sync(0xffffffffu, pu[kc][2], s1);
            unsigned v11 = __shfl_sync(0xffffffffu, pu[kc][3], s1);
            unsigned w00 = __shfl_sync(0xffffffffu, pu[kc][0], s2);
            unsigned w01 = __shfl_sync(0xffffffffu, pu[kc][1], s2);
            unsigned w10 = __shfl_sync(0xffffffffu, pu[kc][2], s2);
            unsigned w11 = __shfl_sync(0xffffffffu, pu[kc][3], s2);
            unsigned pa[4];
            pa[0] = (tg & 1) ? v01 : v00;
            pa[1] = (tg & 1) ? v11 : v10;
            pa[2] = (tg & 1) ? w01 : w00;
            pa[3] = (tg & 1) ? w11 : w10;
#pragma unroll
            for (int ni = 0; ni < 8; ni++) {
                unsigned b0 = Vs[(kc * 8 + tg)     * VSTRD + ni * 8 + gid];
                unsigned b1 = Vs[(kc * 8 + tg + 4) * VSTRD + ni * 8 + gid];
                MMA_TF32(oa[ni], pa, b0, b1);
            }
        }
    };

    for (int kt = 0; kt < qt; kt++) tile_step(kt, false);  // interior: no causal
    tile_step(qt, true);                                    // diagonal

    const float rlA = (lA > 0.f) ? (1.f / lA) : 0.f;
    const float rlB = (lB > 0.f) ? (1.f / lB) : 0.f;
    float* Og = O + (size_t)(tok0 + qb + gid) * DMODEL + h * HDIM;
#pragma unroll
    for (int ni = 0; ni < 8; ni++) {
        int col = ni * 8 + 2 * tg;
        float2 vA = make_float2(oa[ni][0] * rlA, oa[ni][1] * rlA);
        float2 vB = make_float2(oa[ni][2] * rlB, oa[ni][3] * rlB);
        *(float2*)(Og + col) = vA;
        *(float2*)(Og + (size_t)8 * DMODEL + col) = vB;
    }
}

// ---------------------------------------------------------------------------
// Launch
// ---------------------------------------------------------------------------
extern "C" void kernel_launch(void* const* d_in, const int* in_sizes, int n_in,
                              void* d_out, int out_size)
{
    const float* queries = (const float*)d_in[0];
    const float* keys    = (const float*)d_in[1];
    const float* values  = (const float*)d_in[2];
    const unsigned char* maskp = (const unsigned char*)d_in[3];
    const float* Wq = (const float*)d_in[4];
    const float* bq = (const float*)d_in[5];
    const float* Wk = (const float*)d_in[6];
    const float* bk = (const float*)d_in[7];
    const float* Wv = (const float*)d_in[8];
    const float* bv = (const float*)d_in[9];
    const float* Wo = (const float*)d_in[10];
    const float* bo = (const float*)d_in[11];
    float* out = (float*)d_out;

    float *qb, *kb, *vb, *ab;
    cudaGetSymbolAddress((void**)&qb, g_q);
    cudaGetSymbolAddress((void**)&kb, g_k);
    cudaGetSymbolAddress((void**)&vb, g_v);
    cudaGetSymbolAddress((void**)&ab, g_attn);

    cudaFuncSetAttribute(attn_mma,
                         cudaFuncAttributeMaxDynamicSharedMemorySize, ATTN_SMEM);

    // fused Q/K/V projections (grid.z selects problem)
    dim3 gq(DMODEL / GBN, MTOK / GBM, 3);   // (8, 32, 3)
    gemm_tf32<<<gq, 256>>>(
        queries, Wq, bq, qb,
        keys,    Wk, bk, kb,
        values,  Wv, bv, vb,
        MTOK, DMODEL, DMODEL);

    dim3 ga(SEQ / ATS, NHEAD, BATCH);       // (32, 16, 2)
    attn_mma<<<ga, 128, ATTN_SMEM>>>(qb, kb, vb, maskp, ab);

    dim3 go(DMODEL / GBN, MTOK / GBM, 1);   // (8, 32, 1)
    gemm_tf32<<<go, 256>>>(
        ab, Wo, bo, out,
        ab, Wo, bo, out,
        ab, Wo, bo, out,
        MTOK, DMODEL, DMODEL);
}

// round 8
// speedup vs baseline: 1.7203x; 1.1203x over previous
#include <cuda_runtime.h>
#include <cuda_bf16.h>
#include <math.h>

// Problem constants
#define BATCH 2
#define SEQ   2048
#define DMODEL 1024
#define NHEAD 16
#define HDIM  64
#define MTOK  (BATCH*SEQ)        // 4096 tokens

// ---------------------------------------------------------------------------
// Scratch (device globals; allocation-free)
// ---------------------------------------------------------------------------
__device__ float g_q[MTOK * DMODEL];
__device__ float g_k[MTOK * DMODEL];
__device__ float g_v[MTOK * DMODEL];
__device__ float g_attn[MTOK * DMODEL];

__device__ __forceinline__ unsigned f2tf32(float x) {
    unsigned r;
    asm("cvt.rna.tf32.f32 %0, %1;" : "=r"(r) : "f"(x));
    return r;
}

#define MMA_TF32(acc, a, b0, b1)                                           \
    asm volatile(                                                          \
        "mma.sync.aligned.m16n8k8.row.col.f32.tf32.tf32.f32 "              \
        "{%0,%1,%2,%3}, {%4,%5,%6,%7}, {%8,%9}, {%0,%1,%2,%3};"            \
        : "+f"((acc)[0]), "+f"((acc)[1]), "+f"((acc)[2]), "+f"((acc)[3])   \
        : "r"((a)[0]), "r"((a)[1]), "r"((a)[2]), "r"((a)[3]),              \
          "r"(b0), "r"(b1))

#define CP_ASYNC16(dst_u32, src) \
    asm volatile("cp.async.cg.shared.global [%0], [%1], 16;" :: "r"(dst_u32), "l"(src))
#define CP_COMMIT() asm volatile("cp.async.commit_group;")
#define CP_WAIT0()  asm volatile("cp.async.wait_group 0;")

// ---------------------------------------------------------------------------
// TF32 tensor-core GEMM: C = (A@W + bias) * oscale [, tf32-rounded].
// 128x128x32 tile, 256 thr, 8 warps, warp tile 32x64, mma.m16n8k8.
// BSTR=136 -> B-fragment LDS provably bank-conflict-free.
// __launch_bounds__(256,2) -> 2 blocks/SM. blockIdx.z selects problem set.
// ---------------------------------------------------------------------------
#define GBM 128
#define GBN 128
#define GBK 32
#define ASTR 36      // bank = 4*gid+tg  (conflict-free)
#define BSTR 136     // bank = 8*(tg+ni)+gid (conflict-free)

__global__ __launch_bounds__(256, 2) void gemm_tf32(
    const float* __restrict__ A0, const float* __restrict__ W0,
    const float* __restrict__ b0p, float* __restrict__ C0,
    const float* __restrict__ A1, const float* __restrict__ W1,
    const float* __restrict__ b1p, float* __restrict__ C1,
    const float* __restrict__ A2, const float* __restrict__ W2,
    const float* __restrict__ b2p, float* __restrict__ C2,
    float osc0, int round_out,
    int M, int N, int K)
{
    __shared__ unsigned As[GBM * ASTR];   // [m][k]
    __shared__ unsigned Bs[GBK * BSTR];   // [k][n]

    const int z = blockIdx.z;
    const float* A    = (z == 0) ? A0 : (z == 1) ? A1 : A2;
    const float* W    = (z == 0) ? W0 : (z == 1) ? W1 : W2;
    const float* bias = (z == 0) ? b0p : (z == 1) ? b1p : b2p;
    float*       C    = (z == 0) ? C0 : (z == 1) ? C1 : C2;
    const float oscale = (z == 0) ? osc0 : 1.0f;

    const int tid = threadIdx.x;
    const int bm = blockIdx.y * GBM;
    const int bn = blockIdx.x * GBN;

    const int wid  = tid >> 5;
    const int lane = tid & 31;
    const int wm = (wid & 3) * 32;
    const int wn = (wid >> 2) * 64;
    const int gid = lane >> 2;
    const int tg  = lane & 3;

    float acc[2][8][4];
#pragma unroll
    for (int mi = 0; mi < 2; mi++)
#pragma unroll
        for (int ni = 0; ni < 8; ni++)
#pragma unroll
            for (int c = 0; c < 4; c++) acc[mi][ni][c] = 0.f;

    for (int k0 = 0; k0 < K; k0 += GBK) {
#pragma unroll
        for (int i = 0; i < 4; i++) {
            int idx = i * 256 + tid;
            int r  = idx >> 3;
            int c4 = idx & 7;
            float4 v = *(const float4*)(A + (size_t)(bm + r) * K + k0 + c4 * 4);
            unsigned* dst = &As[r * ASTR + c4 * 4];
            dst[0] = f2tf32(v.x); dst[1] = f2tf32(v.y);
            dst[2] = f2tf32(v.z); dst[3] = f2tf32(v.w);
        }
#pragma unroll
        for (int i = 0; i < 4; i++) {
            int idx = i * 256 + tid;
            int k  = idx >> 5;
            int c4 = idx & 31;
            float4 v = *(const float4*)(W + (size_t)(k0 + k) * N + bn + c4 * 4);
            unsigned* dst = &Bs[k * BSTR + c4 * 4];
            dst[0] = f2tf32(v.x); dst[1] = f2tf32(v.y);
            dst[2] = f2tf32(v.z); dst[3] = f2tf32(v.w);
        }
        __syncthreads();

#pragma unroll
        for (int kk = 0; kk < GBK; kk += 8) {
            unsigned af[2][4];
#pragma unroll
            for (int mi = 0; mi < 2; mi++) {
                int rb = wm + mi * 16;
                af[mi][0] = As[(rb + gid) * ASTR + kk + tg];
                af[mi][1] = As[(rb + gid + 8) * ASTR + kk + tg];
                af[mi][2] = As[(rb + gid) * ASTR + kk + tg + 4];
                af[mi][3] = As[(rb + gid + 8) * ASTR + kk + tg + 4];
            }
            unsigned bf[8][2];
#pragma unroll
            for (int ni = 0; ni < 8; ni++) {
                int nb = wn + ni * 8 + gid;
                bf[ni][0] = Bs[(kk + tg) * BSTR + nb];
                bf[ni][1] = Bs[(kk + tg + 4) * BSTR + nb];
            }
#pragma unroll
            for (int mi = 0; mi < 2; mi++)
#pragma unroll
                for (int ni = 0; ni < 8; ni++)
                    MMA_TF32(acc[mi][ni], af[mi], bf[ni][0], bf[ni][1]);
        }
        __syncthreads();
    }

#pragma unroll
    for (int mi = 0; mi < 2; mi++) {
        int row0 = bm + wm + mi * 16 + gid;
#pragma unroll
        for (int ni = 0; ni < 8; ni++) {
            int col = bn + wn + ni * 8 + tg * 2;
            float bb0 = bias[col], bb1 = bias[col + 1];
            float r00 = (acc[mi][ni][0] + bb0) * oscale;
            float r01 = (acc[mi][ni][1] + bb1) * oscale;
            float r10 = (acc[mi][ni][2] + bb0) * oscale;
            float r11 = (acc[mi][ni][3] + bb1) * oscale;
            if (round_out) {
                r00 = __uint_as_float(f2tf32(r00));
                r01 = __uint_as_float(f2tf32(r01));
                r10 = __uint_as_float(f2tf32(r10));
                r11 = __uint_as_float(f2tf32(r11));
            }
            *(float2*)(C + (size_t)row0 * N + col) = make_float2(r00, r01);
            *(float2*)(C + (size_t)(row0 + 8) * N + col) = make_float2(r10, r11);
        }
    }
}

// ---------------------------------------------------------------------------
// Tensor-core flash attention (tf32 mma.m16n8k8), causal-split mainloop.
// Q/K/V arrive pre-rounded to tf32 (and Q pre-scaled) from the projection
// epilogue -> staging is pure cp.async 16B copies, zero conversions.
// ---------------------------------------------------------------------------
#define ATS 64
#define QSTRD 68
#define KSTRD 68
#define VSTRD 72
#define ATTN_SMEM ((ATS*QSTRD + ATS*KSTRD + ATS*VSTRD + ATS) * (int)sizeof(float))

__global__ __launch_bounds__(128) void attn_mma(
    const float* __restrict__ Q, const float* __restrict__ K,
    const float* __restrict__ V, const unsigned char* __restrict__ maskp,
    float* __restrict__ O)
{
    extern __shared__ float sm[];
    unsigned* Qs = (unsigned*)sm;                    // [64][68]
    unsigned* Ks = Qs + ATS * QSTRD;                 // [64][68]
    unsigned* Vs = Ks + ATS * KSTRD;                 // [64][72]
    float*    Madd = (float*)(Vs + ATS * VSTRD);     // [64]

    const int tid  = threadIdx.x;
    const int qt = blockIdx.x, h = blockIdx.y, b = blockIdx.z;
    const int lane = tid & 31, w = tid >> 5;
    const int gid = lane >> 2, tg = lane & 3;
    const int qb = w * 16;
    const int tok0 = b * SEQ + qt * ATS;

    // ---- stage Q (already scaled + tf32-rounded): straight async copy ----
    {
        const float* Qg = Q + (size_t)tok0 * DMODEL + h * HDIM;
#pragma unroll
        for (int i = 0; i < 8; i++) {
            int idx = i * 128 + tid;
            int rr = idx >> 4, c4 = idx & 15;
            unsigned d = (unsigned)__cvta_generic_to_shared(&Qs[rr * QSTRD + c4 * 4]);
            CP_ASYNC16(d, Qg + (size_t)rr * DMODEL + c4 * 4);
        }
        CP_COMMIT();
        CP_WAIT0();
    }
    __syncthreads();

    unsigned qa[8][4];
#pragma unroll
    for (int kc = 0; kc < 8; kc++) {
        qa[kc][0] = Qs[(qb + gid)     * QSTRD + kc * 8 + tg];
        qa[kc][1] = Qs[(qb + gid + 8) * QSTRD + kc * 8 + tg];
        qa[kc][2] = Qs[(qb + gid)     * QSTRD + kc * 8 + tg + 4];
        qa[kc][3] = Qs[(qb + gid + 8) * QSTRD + kc * 8 + tg + 4];
    }

    float oa[8][4];
#pragma unroll
    for (int ni = 0; ni < 8; ni++)
#pragma unroll
        for (int c = 0; c < 4; c++) oa[ni][c] = 0.f;

    float mA = -1e30f, mB = -1e30f, lA = 0.f, lB = 0.f;
    const int rowAg = qt * ATS + qb + gid;
    const int rowBg = rowAg + 8;

    auto tile_step = [&](int kt, bool diag) {
        __syncthreads();
        {
            const float* Kg = K + (size_t)(b * SEQ + kt * ATS) * DMODEL + h * HDIM;
            const float* Vg = V + (size_t)(b * SEQ + kt * ATS) * DMODEL + h * HDIM;
#pragma unroll
            for (int i = 0; i < 8; i++) {
                int idx = i * 128 + tid;
                int rr = idx >> 4, c4 = idx & 15;
                unsigned kd = (unsigned)__cvta_generic_to_shared(&Ks[rr * KSTRD + c4 * 4]);
                CP_ASYNC16(kd, Kg + (size_t)rr * DMODEL + c4 * 4);
                unsigned vd = (unsigned)__cvta_generic_to_shared(&Vs[rr * VSTRD + c4 * 4]);
                CP_ASYNC16(vd, Vg + (size_t)rr * DMODEL + c4 * 4);
            }
            CP_COMMIT();
            if (tid < ATS)
                Madd[tid] = maskp[b * SEQ + kt * ATS + tid] ? -1e30f : 0.f;
            CP_WAIT0();
        }
        __syncthreads();

        float sacc[8][4];
#pragma unroll
        for (int ni = 0; ni < 8; ni++)
#pragma unroll
            for (int c = 0; c < 4; c++) sacc[ni][c] = 0.f;
#pragma unroll
        for (int kc = 0; kc < 8; kc++) {
#pragma unroll
            for (int ni = 0; ni < 8; ni++) {
                unsigned b0 = Ks[(ni * 8 + gid) * KSTRD + kc * 8 + tg];
                unsigned b1 = Ks[(ni * 8 + gid) * KSTRD + kc * 8 + tg + 4];
                MMA_TF32(sacc[ni], qa[kc], b0, b1);
            }
        }

        const int kbase = kt * ATS;
        float tmA = -1e30f, tmB = -1e30f;
#pragma unroll
        for (int ni = 0; ni < 8; ni++) {
            int c0 = ni * 8 + 2 * tg, c1 = c0 + 1;
            float m0 = Madd[c0], m1 = Madd[c1];
            sacc[ni][0] += m0; sacc[ni][1] += m1;
            sacc[ni][2] += m0; sacc[ni][3] += m1;
            if (diag) {
                if (kbase + c0 > rowAg) sacc[ni][0] = -1e30f;
                if (kbase + c1 > rowAg) sacc[ni][1] = -1e30f;
                if (kbase + c0 > rowBg) sacc[ni][2] = -1e30f;
                if (kbase + c1 > rowBg) sacc[ni][3] = -1e30f;
            }
            tmA = fmaxf(tmA, fmaxf(sacc[ni][0], sacc[ni][1]));
            tmB = fmaxf(tmB, fmaxf(sacc[ni][2], sacc[ni][3]));
        }
        tmA = fmaxf(tmA, __shfl_xor_sync(0xffffffffu, tmA, 1));
        tmA = fmaxf(tmA, __shfl_xor_sync(0xffffffffu, tmA, 2));
        tmB = fmaxf(tmB, __shfl_xor_sync(0xffffffffu, tmB, 1));
        tmB = fmaxf(tmB, __shfl_xor_sync(0xffffffffu, tmB, 2));

        float nmA = fmaxf(mA, tmA), nmB = fmaxf(mB, tmB);
        float corrA = (mA > -1e29f) ? __expf(mA - nmA) : 0.f;
        float corrB = (mB > -1e29f) ? __expf(mB - nmB) : 0.f;

        unsigned pu[8][4];
        float saA = 0.f, saB = 0.f;
#pragma unroll
        for (int ni = 0; ni < 8; ni++) {
            float p0 = (sacc[ni][0] > -1e29f) ? __expf(sacc[ni][0] - nmA) : 0.f;
            float p1 = (sacc[ni][1] > -1e29f) ? __expf(sacc[ni][1] - nmA) : 0.f;
            float p2 = (sacc[ni][2] > -1e29f) ? __expf(sacc[ni][2] - nmB) : 0.f;
            float p3 = (sacc[ni][3] > -1e29f) ? __expf(sacc[ni][3] - nmB) : 0.f;
            saA += p0 + p1; saB += p2 + p3;
            pu[ni][0] = f2tf32(p0); pu[ni][1] = f2tf32(p1);
            pu[ni][2] = f2tf32(p2); pu[ni][3] = f2tf32(p3);
        }
        saA += __shfl_xor_sync(0xffffffffu, saA, 1);
        saA += __shfl_xor_sync(0xffffffffu, saA, 2);
        saB += __shfl_xor_sync(0xffffffffu, saB, 1);
        saB += __shfl_xor_sync(0xffffffffu, saB, 2);

        lA = lA * corrA + saA;
        lB = lB * corrB + saB;
        mA = nmA; mB = nmB;
#pragma unroll
        for (int ni = 0; ni < 8; ni++) {
            oa[ni][0] *= corrA; oa[ni][1] *= corrA;
            oa[ni][2] *= corrB; oa[ni][3] *= corrB;
        }

        const int srcbase = lane & ~3;
#pragma unroll
        for (int kc = 0; kc < 8; kc++) {
            int s1 = srcbase + (tg >> 1);
            int s2 = s1 + 2;
            unsigned v00 = __shfl_sync(0xffffffffu, pu[kc][0], s1);
            unsigned v01 = __shfl_sync(0xffffffffu, pu[kc][1], s1);
            unsigned v10 = __shfl_sync(0xffffffffu, pu[kc][2], s1);
            unsigned v11 = __shfl_sync(0xffffffffu, pu[kc][3], s1);
            unsigned w00 = __shfl_sync(0xffffffffu, pu[kc][0], s2);
            unsigned w01 = __shfl_sync(0xffffffffu, pu[kc][1], s2);
            unsigned w10 = __shfl_sync(0xffffffffu, pu[kc][2], s2);
            unsigned w11 = __shfl_sync(0xffffffffu, pu[kc][3], s2);
            unsigned pa[4];
            pa[0] = (tg & 1) ? v01 : v00;
            pa[1] = (tg & 1) ? v11 : v10;
            pa[2] = (tg & 1) ? w01 : w00;
            pa[3] = (tg & 1) ? w11 : w10;
#pragma unroll
            for (int ni = 0; ni < 8; ni++) {
                unsigned b0 = Vs[(kc * 8 + tg)     * VSTRD + ni * 8 + gid];
                unsigned b1 = Vs[(kc * 8 + tg + 4) * VSTRD + ni * 8 + gid];
                MMA_TF32(oa[ni], pa, b0, b1);
            }
        }
    };

    for (int kt = 0; kt < qt; kt++) tile_step(kt, false);  // interior
    tile_step(qt, true);                                    // diagonal

    const float rlA = (lA > 0.f) ? (1.f / lA) : 0.f;
    const float rlB = (lB > 0.f) ? (1.f / lB) : 0.f;
    float* Og = O + (size_t)(tok0 + qb + gid) * DMODEL + h * HDIM;
#pragma unroll
    for (int ni = 0; ni < 8; ni++) {
        int col = ni * 8 + 2 * tg;
        float2 vA = make_float2(oa[ni][0] * rlA, oa[ni][1] * rlA);
        float2 vB = make_float2(oa[ni][2] * rlB, oa[ni][3] * rlB);
        *(float2*)(Og + col) = vA;
        *(float2*)(Og + (size_t)8 * DMODEL + col) = vB;
    }
}

// ---------------------------------------------------------------------------
// Launch
// ---------------------------------------------------------------------------
extern "C" void kernel_launch(void* const* d_in, const int* in_sizes, int n_in,
                              void* d_out, int out_size)
{
    const float* queries = (const float*)d_in[0];
    const float* keys    = (const float*)d_in[1];
    const float* values  = (const float*)d_in[2];
    const unsigned char* maskp = (const unsigned char*)d_in[3];
    const float* Wq = (const float*)d_in[4];
    const float* bq = (const float*)d_in[5];
    const float* Wk = (const float*)d_in[6];
    const float* bk = (const float*)d_in[7];
    const float* Wv = (const float*)d_in[8];
    const float* bv = (const float*)d_in[9];
    const float* Wo = (const float*)d_in[10];
    const float* bo = (const float*)d_in[11];
    float* out = (float*)d_out;

    float *qb, *kb, *vb, *ab;
    cudaGetSymbolAddress((void**)&qb, g_q);
    cudaGetSymbolAddress((void**)&kb, g_k);
    cudaGetSymbolAddress((void**)&vb, g_v);
    cudaGetSymbolAddress((void**)&ab, g_attn);

    cudaFuncSetAttribute(attn_mma,
                         cudaFuncAttributeMaxDynamicSharedMemorySize, ATTN_SMEM);

    // fused Q/K/V projections; outputs tf32-rounded, Q pre-scaled by 1/8
    dim3 gq(DMODEL / GBN, MTOK / GBM, 3);   // (8, 32, 3)
    gemm_tf32<<<gq, 256>>>(
        queries, Wq, bq, qb,
        keys,    Wk, bk, kb,
        values,  Wv, bv, vb,
        0.125f, 1,
        MTOK, DMODEL, DMODEL);

    dim3 ga(SEQ / ATS, NHEAD, BATCH);       // (32, 16, 2)
    attn_mma<<<ga, 128, ATTN_SMEM>>>(qb, kb, vb, maskp, ab);

    dim3 go(DMODEL / GBN, MTOK / GBM, 1);   // (8, 32, 1)
    gemm_tf32<<<go, 256>>>(
        ab, Wo, bo, out,
        ab, Wo, bo, out,
        ab, Wo, bo, out,
        1.0f, 0,
        MTOK, DMODEL, DMODEL);
}